// round 2
// baseline (speedup 1.0000x reference)
#include <cuda_runtime.h>
#include <cstdint>

// ---------------------------------------------------------------------------
// Problem constants (shapes fixed by the dataset)
// B=32, H=W=64, C=256, HEADS=8, HEAD_DIM=32, CW=CH=4 (M=16), WW=WH=2
// => b3 = 1024 cluster blocks, each viewing a flat 32768-float slab as
//    [c3=32, L=1024] (xh) or [L=1024, c3=32] (value/feature), M=16 centers.
// ---------------------------------------------------------------------------
#define TOK_TOTAL 131072          // 32 * 4096 tokens
#define CIN 256
#define ELEMS 33554432            // 32*256*64*64

// Scratch (device globals: no runtime allocation allowed)
__device__ float g_xh[ELEMS];
__device__ float g_val[ELEMS];
__device__ float g_feat[ELEMS];
__device__ float g_mid[ELEMS];
__device__ float g_centers[1024 * 512];
__device__ float g_cfeat[1024 * 512];

// ---------------------------------------------------------------------------
// Kernel A: fused input convs.  out[o, t] = sum_k W[o,k] * x[t,k] + b[o]
// Output layout per conv: [B, O, HW] i.e. flat (b*256+o)*4096 + n.
// Tiling: 128 (o) x 128 (t) x 8 (k); 256 threads, 8x8 microtile.
// grid.x = 6 o-tiles (2 per conv), grid.y = 1024 t-tiles.
// ---------------------------------------------------------------------------
__global__ void __launch_bounds__(256) conv_in_kernel(
    const float* __restrict__ x,
    const float* __restrict__ w1, const float* __restrict__ b1,
    const float* __restrict__ wv, const float* __restrict__ bv,
    const float* __restrict__ wf, const float* __restrict__ bf,
    float* __restrict__ xh, float* __restrict__ val, float* __restrict__ feat)
{
    __shared__ __align__(16) float Ws[8][128];
    __shared__ __align__(16) float Xs[8][128];

    const int tid = threadIdx.x;
    const int tx = tid & 15;         // t microtile
    const int ty = tid >> 4;         // o microtile
    const int bx = blockIdx.x;       // o tile (0..5)
    const int jBase = blockIdx.y * 128;

    const int conv = bx >> 1;                 // 0:conv1, 1:convv, 2:convf
    const int oo_base = (bx & 1) * 128;

    const float* wsel; const float* bsel; float* osel;
    if (conv == 0)      { wsel = w1; bsel = b1; osel = xh;  }
    else if (conv == 1) { wsel = wv; bsel = bv; osel = val; }
    else                { wsel = wf; bsel = bf; osel = feat;}

    const int lw_i = tid >> 1;
    const int lw_k = (tid & 1) * 4;
    const float* wrow = wsel + (size_t)(oo_base + lw_i) * CIN + lw_k;
    const float* xrow = x    + (size_t)(jBase  + lw_i) * CIN + lw_k;

    float acc[8][8];
    #pragma unroll
    for (int v = 0; v < 8; v++)
        #pragma unroll
        for (int u = 0; u < 8; u++) acc[v][u] = 0.f;

    for (int kk = 0; kk < CIN; kk += 8) {
        float4 wa = *(const float4*)(wrow + kk);
        float4 xa = *(const float4*)(xrow + kk);
        Ws[lw_k + 0][lw_i] = wa.x; Ws[lw_k + 1][lw_i] = wa.y;
        Ws[lw_k + 2][lw_i] = wa.z; Ws[lw_k + 3][lw_i] = wa.w;
        Xs[lw_k + 0][lw_i] = xa.x; Xs[lw_k + 1][lw_i] = xa.y;
        Xs[lw_k + 2][lw_i] = xa.z; Xs[lw_k + 3][lw_i] = xa.w;
        __syncthreads();
        #pragma unroll
        for (int k = 0; k < 8; k++) {
            float a[8], bb[8];
            *(float4*)(a)      = *(const float4*)&Ws[k][ty * 8];
            *(float4*)(a + 4)  = *(const float4*)&Ws[k][ty * 8 + 4];
            *(float4*)(bb)     = *(const float4*)&Xs[k][tx * 8];
            *(float4*)(bb + 4) = *(const float4*)&Xs[k][tx * 8 + 4];
            #pragma unroll
            for (int v = 0; v < 8; v++)
                #pragma unroll
                for (int u = 0; u < 8; u++) acc[v][u] += a[v] * bb[u];
        }
        __syncthreads();
    }

    const int b  = jBase >> 12;
    const int n0 = (jBase & 4095) + tx * 8;
    #pragma unroll
    for (int v = 0; v < 8; v++) {
        const int o = oo_base + ty * 8 + v;
        const float bias = bsel[o];
        float* dst = osel + ((size_t)b * 256 + o) * 4096 + n0;
        float4 r0, r1;
        r0.x = acc[v][0] + bias; r0.y = acc[v][1] + bias;
        r0.z = acc[v][2] + bias; r0.w = acc[v][3] + bias;
        r1.x = acc[v][4] + bias; r1.y = acc[v][5] + bias;
        r1.z = acc[v][6] + bias; r1.w = acc[v][7] + bias;
        *(float4*)(dst)     = r0;
        *(float4*)(dst + 4) = r1;
    }
}

// ---------------------------------------------------------------------------
// Kernel B: adaptive 4x4 average pools of xh and feature, per b3 slab.
// pooled[b3, c, cw*4+ch] = mean over 8x8 block of [32,32] spatial.
// ---------------------------------------------------------------------------
__global__ void __launch_bounds__(256) pool_kernel(
    const float* __restrict__ xh, const float* __restrict__ feat,
    float* __restrict__ centers, float* __restrict__ cfeat)
{
    const int b = blockIdx.x;
    const int tid = threadIdx.x;
    __shared__ float row[1024];
    const size_t base = (size_t)b * 32768;

    for (int src = 0; src < 2; src++) {
        const float* p = src ? feat : xh;
        float* o = src ? cfeat : centers;
        for (int c = 0; c < 32; c++) {
            #pragma unroll
            for (int r = 0; r < 4; r++)
                row[tid + r * 256] = p[base + (size_t)c * 1024 + tid + r * 256];
            __syncthreads();
            const int bin = tid >> 4, s = tid & 15;
            const int w0 = (bin >> 2) * 8, h0 = (bin & 3) * 8;
            float part = 0.f;
            #pragma unroll
            for (int q = 0; q < 4; q++) {
                const int e = s * 4 + q;
                part += row[(w0 + (e >> 3)) * 32 + h0 + (e & 7)];
            }
            #pragma unroll
            for (int off = 8; off; off >>= 1)
                part += __shfl_down_sync(0xffffffffu, part, off, 16);
            if (s == 0) o[b * 512 + c * 16 + bin] = part * (1.f / 64.f);
            __syncthreads();
        }
    }
}

// ---------------------------------------------------------------------------
// Kernel C: full clustering pipeline, one CTA per b3.
// ---------------------------------------------------------------------------
__global__ void __launch_bounds__(256) cluster_kernel(
    const float* __restrict__ xh, const float* __restrict__ val,
    const float* __restrict__ feat, const float* __restrict__ centers,
    const float* __restrict__ cfeat,
    const float* __restrict__ wc, const float* __restrict__ bc,
    const float* __restrict__ alpha_p, const float* __restrict__ beta_p,
    float* __restrict__ outm)
{
    const int b = blockIdx.x;
    const int tid = threadIdx.x;
    const size_t base = (size_t)b * 32768;

    __shared__ float buf[128 * 33];          // value / xh(T) / feature chunks
    __shared__ float sim_s[16 * 128];        // sim for current chunk
    __shared__ float cenn[512];              // normalized centers (phase1/3)
    __shared__ float cc2[512];               // centers2 / oc
    __shared__ float s_s[1024];              // per-token max sigmoid
    __shared__ unsigned char ms_s[1024];     // per-token argmax m
    __shared__ float rn[128];                // per-token 1/norm (reused)
    __shared__ int cnt[16];

    // ---- Phase 0: cen = l2norm(convc(centers)) (raw-reshape aware) ----
    buf[tid]       = centers[b * 512 + tid];
    buf[tid + 256] = centers[b * 512 + tid + 256];
    __syncthreads();
    #pragma unroll
    for (int rep = 0; rep < 2; rep++) {
        const int j = tid + rep * 256;
        const int co = j >> 4, pos = j & 15;
        float a = bc[co];
        #pragma unroll
        for (int ci = 0; ci < 32; ci++) a += wc[co * 32 + ci] * buf[ci * 16 + pos];
        cc2[j] = a;          // flat [co,pos]; cen[m,c] = cc2[m*32+c] (raw reshape)
    }
    __syncthreads();
    if (tid < 16) {
        float ss = 0.f;
        #pragma unroll
        for (int c = 0; c < 32; c++) { float v = cc2[tid * 32 + c]; ss += v * v; }
        rn[tid] = 1.f / fmaxf(sqrtf(ss), 1e-12f);
    }
    __syncthreads();
    cenn[tid]       = cc2[tid]       * rn[tid >> 5];
    cenn[tid + 256] = cc2[tid + 256] * rn[(tid + 256) >> 5];
    __syncthreads();

    const int m0 = tid >> 5, cc = tid & 31;
    float acc0 = 0.f, acc1 = 0.f;

    // ---- Phase 1: sim1 softmax + centers2 = sim1 @ feature ----
    for (int ch = 0; ch < 8; ch++) {
        const int l0 = ch * 128;
        #pragma unroll
        for (int r = 0; r < 16; r++) {
            const int g = tid + r * 256;
            buf[(g >> 5) * 33 + (g & 31)] = val[base + l0 * 32 + g];
        }
        __syncthreads();
        if (tid < 128) {
            float ss = 0.f;
            #pragma unroll
            for (int c = 0; c < 32; c++) { float v = buf[tid * 33 + c]; ss += v * v; }
            rn[tid] = 1.f / fmaxf(sqrtf(ss), 1e-12f);
        }
        __syncthreads();
        {
            const int l = tid & 127, mh = (tid >> 7) * 8;
            const float r = rn[l];
            #pragma unroll
            for (int mm = 0; mm < 8; mm++) {
                const int m = mh + mm;
                float d = 0.f;
                #pragma unroll
                for (int c = 0; c < 32; c++) d += cenn[m * 32 + c] * buf[l * 33 + c];
                sim_s[m * 128 + l] = d * r;
            }
        }
        __syncthreads();
        if (tid < 128) {
            const int l = tid;
            float mx = -1e30f;
            #pragma unroll
            for (int m = 0; m < 16; m++) mx = fmaxf(mx, sim_s[m * 128 + l]);
            float e[16], sum = 0.f;
            #pragma unroll
            for (int m = 0; m < 16; m++) { e[m] = expf(sim_s[m * 128 + l] - mx); sum += e[m]; }
            const float inv = 1.f / sum;
            #pragma unroll
            for (int m = 0; m < 16; m++) sim_s[m * 128 + l] = e[m] * inv;
        }
        __syncthreads();
        #pragma unroll
        for (int r = 0; r < 16; r++) {
            const int g = tid + r * 256;
            buf[(g >> 5) * 33 + (g & 31)] = feat[base + l0 * 32 + g];
        }
        __syncthreads();
        #pragma unroll 4
        for (int l = 0; l < 128; l++) {
            const float f = buf[l * 33 + cc];
            acc0 += sim_s[m0 * 128 + l] * f;
            acc1 += sim_s[(m0 + 8) * 128 + l] * f;
        }
        __syncthreads();
    }
    cc2[m0 * 32 + cc]       = acc0;     // centers2 flat [m,c]
    cc2[(m0 + 8) * 32 + cc] = acc1;
    __syncthreads();

    // ---- Phase 2: cen2[m,c] = centers2_flat[c*16+m], l2norm over c ----
    if (tid < 16) {
        float ss = 0.f;
        #pragma unroll
        for (int c = 0; c < 32; c++) { float v = cc2[c * 16 + tid]; ss += v * v; }
        rn[tid] = 1.f / fmaxf(sqrtf(ss), 1e-12f);
        cnt[tid] = 0;
    }
    __syncthreads();
    #pragma unroll
    for (int rep = 0; rep < 2; rep++) {
        const int j = tid + rep * 256;
        const int m = j >> 5, c = j & 31;
        cenn[j] = cc2[c * 16 + m] * rn[m];
    }
    const float alpha = alpha_p[0], beta = beta_p[0];
    float agg0 = 0.f, agg1 = 0.f;
    __syncthreads();

    // ---- Phase 3: sim2 sigmoid + first-argmax + masked agg ----
    for (int ch = 0; ch < 8; ch++) {
        const int l0 = ch * 128;
        #pragma unroll
        for (int r = 0; r < 16; r++) {
            const int g = tid + r * 256;              // g = c*128 + lo
            const int c = g >> 7, lo = g & 127;
            buf[lo * 33 + c] = xh[base + (size_t)c * 1024 + l0 + lo];
        }
        __syncthreads();
        if (tid < 128) {
            float ss = 0.f;
            #pragma unroll
            for (int c = 0; c < 32; c++) { float v = buf[tid * 33 + c]; ss += v * v; }
            rn[tid] = 1.f / fmaxf(sqrtf(ss), 1e-12f);
        }
        #pragma unroll
        for (int r = 0; r < 8; r++) sim_s[tid + r * 256] = 0.f;
        __syncthreads();
        if (tid < 128) {
            const int l = tid;
            const float r = rn[l];
            float best = -1.f; int bm = 0;
            #pragma unroll
            for (int m = 0; m < 16; m++) {
                float d = 0.f;
                #pragma unroll
                for (int c = 0; c < 32; c++) d += cenn[m * 32 + c] * buf[l * 33 + c];
                const float z = beta + alpha * (d * r);
                const float s = 1.f / (1.f + expf(-z));
                if (s > best) { best = s; bm = m; }
            }
            sim_s[bm * 128 + l] = best;
            s_s[l0 + l] = best;
            ms_s[l0 + l] = (unsigned char)bm;
            atomicAdd(&cnt[bm], 1);
        }
        __syncthreads();
        #pragma unroll
        for (int r = 0; r < 16; r++) {
            const int g = tid + r * 256;
            buf[(g >> 5) * 33 + (g & 31)] = feat[base + l0 * 32 + g];
        }
        __syncthreads();
        #pragma unroll 4
        for (int l = 0; l < 128; l++) {
            const float f = buf[l * 33 + cc];
            agg0 += sim_s[m0 * 128 + l] * f;
            agg1 += sim_s[(m0 + 8) * 128 + l] * f;
        }
        __syncthreads();
    }

    // ---- Phase 4: oc = (agg + centers_feature) / (count + 1) ----
    cc2[m0 * 32 + cc] =
        (agg0 + cfeat[b * 512 + m0 * 32 + cc]) / ((float)cnt[m0] + 1.f);
    cc2[(m0 + 8) * 32 + cc] =
        (agg1 + cfeat[b * 512 + (m0 + 8) * 32 + cc]) / ((float)cnt[m0 + 8] + 1.f);
    __syncthreads();

    // ---- Phase 5: dispatch out[l,c] = s_l * oc[m_l, c] ----
    #pragma unroll 8
    for (int r = 0; r < 128; r++) {
        const int idx = tid + r * 256;
        const int l = idx >> 5, c = idx & 31;
        outm[base + idx] = s_s[l] * cc2[(int)ms_s[l] * 32 + c];
    }
}

// ---------------------------------------------------------------------------
// Kernel D: conv2.  final[t, o] = sum_k W2[o,k] * mid[b,k,n] + b2[o]
// mid is k-strided (stride 4096 along k); output row-major along o.
// ---------------------------------------------------------------------------
__global__ void __launch_bounds__(256) conv_out_kernel(
    const float* __restrict__ mid, const float* __restrict__ w2,
    const float* __restrict__ b2, float* __restrict__ outp)
{
    __shared__ __align__(16) float As[8][128];   // [k][t]
    __shared__ __align__(16) float Bs[8][128];   // [k][o]

    const int tid = threadIdx.x;
    const int tx = tid & 15;        // o microtile
    const int ty = tid >> 4;        // t microtile
    const int oBase = blockIdx.x * 128;
    const int tBase = blockIdx.y * 128;
    const int b = tBase >> 12;
    const int n0 = tBase & 4095;

    const int la_k = tid >> 5;              // 0..7
    const int la_t4 = (tid & 31) * 4;       // 0..124
    const float* arow = mid + (size_t)b * 256 * 4096 + n0 + la_t4;

    const int lb_o = tid >> 1;
    const int lb_k = (tid & 1) * 4;
    const float* brow = w2 + (size_t)(oBase + lb_o) * 256 + lb_k;

    float acc[8][8];
    #pragma unroll
    for (int v = 0; v < 8; v++)
        #pragma unroll
        for (int u = 0; u < 8; u++) acc[v][u] = 0.f;

    for (int kk = 0; kk < 256; kk += 8) {
        const float4 av = *(const float4*)(arow + (size_t)(kk + la_k) * 4096);
        const float4 bv = *(const float4*)(brow + kk);
        *(float4*)&As[la_k][la_t4] = av;
        Bs[lb_k + 0][lb_o] = bv.x; Bs[lb_k + 1][lb_o] = bv.y;
        Bs[lb_k + 2][lb_o] = bv.z; Bs[lb_k + 3][lb_o] = bv.w;
        __syncthreads();
        #pragma unroll
        for (int k = 0; k < 8; k++) {
            float a[8], bb[8];
            *(float4*)(a)      = *(const float4*)&As[k][ty * 8];
            *(float4*)(a + 4)  = *(const float4*)&As[k][ty * 8 + 4];
            *(float4*)(bb)     = *(const float4*)&Bs[k][tx * 8];
            *(float4*)(bb + 4) = *(const float4*)&Bs[k][tx * 8 + 4];
            #pragma unroll
            for (int v = 0; v < 8; v++)
                #pragma unroll
                for (int u = 0; u < 8; u++) acc[v][u] += a[v] * bb[u];
        }
        __syncthreads();
    }

    float bias[8];
    #pragma unroll
    for (int u = 0; u < 8; u++) bias[u] = b2[oBase + tx * 8 + u];

    #pragma unroll
    for (int v = 0; v < 8; v++) {
        const int t = tBase + ty * 8 + v;
        float* dst = outp + (size_t)t * 256 + oBase + tx * 8;
        float4 r0, r1;
        r0.x = acc[v][0] + bias[0]; r0.y = acc[v][1] + bias[1];
        r0.z = acc[v][2] + bias[2]; r0.w = acc[v][3] + bias[3];
        r1.x = acc[v][4] + bias[4]; r1.y = acc[v][5] + bias[5];
        r1.z = acc[v][6] + bias[6]; r1.w = acc[v][7] + bias[7];
        *(float4*)(dst)     = r0;
        *(float4*)(dst + 4) = r1;
    }
}

// ---------------------------------------------------------------------------
extern "C" void kernel_launch(void* const* d_in, const int* in_sizes, int n_in,
                              void* d_out, int out_size)
{
    // Input order (metadata): x, H, W, conv1_w, conv1_b, conv2_w, conv2_b,
    //                         convc_w, convc_b, convv_w, convv_b,
    //                         convf_w, convf_b, sim_alpha, sim_beta
    int o = 0;
    if (n_in == 13) o = -2;   // fallback: H, W scalars not materialized

    const float* x   = (const float*)d_in[0];
    const float* w1  = (const float*)d_in[3 + o];
    const float* b1  = (const float*)d_in[4 + o];
    const float* w2  = (const float*)d_in[5 + o];
    const float* b2  = (const float*)d_in[6 + o];
    const float* wc  = (const float*)d_in[7 + o];
    const float* bc  = (const float*)d_in[8 + o];
    const float* wv  = (const float*)d_in[9 + o];
    const float* bv  = (const float*)d_in[10 + o];
    const float* wf  = (const float*)d_in[11 + o];
    const float* bf  = (const float*)d_in[12 + o];
    const float* al  = (const float*)d_in[13 + o];
    const float* be  = (const float*)d_in[14 + o];

    void *p_xh, *p_val, *p_feat, *p_mid, *p_cen, *p_cf;
    cudaGetSymbolAddress(&p_xh, g_xh);
    cudaGetSymbolAddress(&p_val, g_val);
    cudaGetSymbolAddress(&p_feat, g_feat);
    cudaGetSymbolAddress(&p_mid, g_mid);
    cudaGetSymbolAddress(&p_cen, g_centers);
    cudaGetSymbolAddress(&p_cf, g_cfeat);
    float* xh   = (float*)p_xh;
    float* val  = (float*)p_val;
    float* feat = (float*)p_feat;
    float* mid  = (float*)p_mid;
    float* cen  = (float*)p_cen;
    float* cf   = (float*)p_cf;

    conv_in_kernel<<<dim3(6, 1024), 256>>>(x, w1, b1, wv, bv, wf, bf,
                                           xh, val, feat);
    pool_kernel<<<1024, 256>>>(xh, feat, cen, cf);
    cluster_kernel<<<1024, 256>>>(xh, val, feat, cen, cf, wc, bc, al, be, mid);
    conv_out_kernel<<<dim3(2, 1024), 256>>>(mid, w2, b2, (float*)d_out);
}